// round 8
// baseline (speedup 1.0000x reference)
#include <cuda_runtime.h>
#include <cstdint>

// SparseStateAggregator, pipelined: dots for token t+1 (vs C_{t-1}) are computed
// and all-gathered during iteration t; the decision for token t uses dots shipped
// one iteration earlier plus a rank-1 correction for the single row updated at t-1.
// kk[t]=dot(k_t,k_{t-1}) and kn2[t]=||k_t||^2 precomputed by a parallel kernel.

#define D_DIM   1024
#define M_ST    64
#define RANKS   8
#define COLS    128
#define TPB     256
#define THRESH_F 0.9f
#define EPS_F   1e-12f

// ---- shared memory layout (bytes) ----
#define OFF_MBAR   0       // 4 x u64 mbarriers (4-deep token ring)
#define OFF_INTS   32      // [0]=slot [1]=create
#define OFF_DENOM  48      // float
#define OFF_COUNTS 64      // 64 floats
#define OFF_CNORM2 320     // 64 floats
#define OFF_SQ4    576     // 4 floats (per-warp sq partials of updated cent row)
#define OFF_KSH    640     // 2 x 128 floats (ping-pong token keys)
#define OFF_VSH    1664    // 2 x 128 floats (ping-pong token values)
#define OFF_RECV   2688    // float recv[4][8][66]: 0..63 dot partials, 64 cn2 partial
#define OFF_CENT   11136   // 64*128 floats
#define OFF_STAT   43904   // 64*128 floats
#define SMEM_BYTES 76672

__device__ float g_kn2[65536];
__device__ float g_kk[65536];

static __device__ __forceinline__ uint32_t smem_u32(const void* p) {
    uint32_t a;
    asm("{ .reg .u64 t; cvta.to.shared.u64 t, %1; cvt.u32.u64 %0, t; }"
        : "=r"(a) : "l"(p));
    return a;
}
static __device__ __forceinline__ uint32_t mapa_rank(uint32_t addr, uint32_t rank) {
    uint32_t ra;
    asm("mapa.shared::cluster.u32 %0, %1, %2;" : "=r"(ra) : "r"(addr), "r"(rank));
    return ra;
}
static __device__ __forceinline__ void st_dsmem(uint32_t addr, float v) {
    asm volatile("st.shared::cluster.f32 [%0], %1;" :: "r"(addr), "f"(v) : "memory");
}
static __device__ __forceinline__ void mbar_init(uint32_t addr, uint32_t cnt) {
    asm volatile("mbarrier.init.shared.b64 [%0], %1;" :: "r"(addr), "r"(cnt) : "memory");
}
static __device__ __forceinline__ void mbar_arrive_remote(uint32_t local_mbar, uint32_t rank) {
    uint32_t ra = mapa_rank(local_mbar, rank);
    asm volatile("mbarrier.arrive.release.cluster.shared::cluster.b64 _, [%0];"
                 :: "r"(ra) : "memory");
}
static __device__ __forceinline__ void mbar_wait_cluster(uint32_t mbar, uint32_t parity) {
    asm volatile(
        "{\n\t"
        ".reg .pred P1;\n\t"
        "LAB_WAIT_%=:\n\t"
        "mbarrier.try_wait.parity.acquire.cluster.shared::cta.b64 P1, [%0], %1;\n\t"
        "@!P1 bra LAB_WAIT_%=;\n\t"
        "}\n"
        :: "r"(mbar), "r"(parity) : "memory");
}
static __device__ __forceinline__ void cluster_sync_all() {
    asm volatile("barrier.cluster.arrive.aligned;" ::: "memory");
    asm volatile("barrier.cluster.wait.aligned;" ::: "memory");
}

// ---- precompute: kn2[t]=||k_t||^2, kk[t]=dot(k_t,k_{t-1}) (kk[0]=0) ----
__global__ void __launch_bounds__(256) precompute_kernel(const float* __restrict__ keys, int S) {
    const int tok = blockIdx.x;
    const int t = tok - (tok / S) * S;
    const float4* kt = (const float4*)(keys + (size_t)tok * D_DIM);
    const float4 a = kt[threadIdx.x];
    float kn = a.x * a.x + a.y * a.y + a.z * a.z + a.w * a.w;
    float kk = 0.0f;
    if (t > 0) {
        const float4 p = ((const float4*)(keys + (size_t)(tok - 1) * D_DIM))[threadIdx.x];
        kk = a.x * p.x + a.y * p.y + a.z * p.z + a.w * p.w;
    }
    #pragma unroll
    for (int off = 16; off; off >>= 1) {
        kn += __shfl_xor_sync(0xffffffffu, kn, off);
        kk += __shfl_xor_sync(0xffffffffu, kk, off);
    }
    __shared__ float skn[8], skk[8];
    const int wid = threadIdx.x >> 5, lane = threadIdx.x & 31;
    if (lane == 0) { skn[wid] = kn; skk[wid] = kk; }
    __syncthreads();
    if (threadIdx.x == 0) {
        float a0 = 0.0f, b0 = 0.0f;
        #pragma unroll
        for (int i = 0; i < 8; ++i) { a0 += skn[i]; b0 += skk[i]; }
        g_kn2[tok] = a0; g_kk[tok] = b0;
    }
}

__global__ void __cluster_dims__(RANKS, 1, 1) __launch_bounds__(TPB, 1)
sparse_agg_kernel(const float* __restrict__ keys,
                  const float* __restrict__ values,
                  float* __restrict__ out, int S)
{
    extern __shared__ unsigned char sm[];
    const uint32_t sbase = smem_u32(sm);

    const int tid  = threadIdx.x;
    const int wid  = tid >> 5;
    const int lane = tid & 31;
    const int rank = blockIdx.x & (RANKS - 1);
    const int b    = blockIdx.x >> 3;
    const int c0   = rank * COLS;

    const float* kb = keys   + (size_t)b * S * D_DIM + c0;
    const float* vb = values + (size_t)b * S * D_DIM + c0;
    const size_t gbase = (size_t)b * S;

    float* cent   = (float*)(sm + OFF_CENT);
    float* stat   = (float*)(sm + OFF_STAT);
    float* counts = (float*)(sm + OFF_COUNTS);
    float* cn2    = (float*)(sm + OFF_CNORM2);
    float* sq4    = (float*)(sm + OFF_SQ4);
    float* kshf   = (float*)(sm + OFF_KSH);
    float* vshf   = (float*)(sm + OFF_VSH);
    float* recvf  = (float*)(sm + OFF_RECV);
    int*   shi    = (int*)  (sm + OFF_INTS);
    float* shden  = (float*)(sm + OFF_DENOM);

    // ---- init ----
    for (int i = tid; i < M_ST * COLS; i += TPB) { cent[i] = 0.0f; stat[i] = 0.0f; }
    for (int i = tid; i < M_ST; i += TPB) { counts[i] = 0.0f; cn2[i] = 0.0f; }
    for (int i = tid; i < 4 * 8 * 66; i += TPB) recvf[i] = 0.0f;
    if (tid < 4) sq4[tid] = 0.0f;
    if (tid == 0) {
        #pragma unroll
        for (int m = 0; m < 4; ++m)
            mbar_init(sbase + OFF_MBAR + 8u * m, 56);   // 7 peers * 8 warps
    }
    // preload tokens 0,1 into ping-pong buffers, token 2 into regs
    if (tid < 128) {
        kshf[tid] = kb[tid];
        if (S > 1) kshf[128 + tid] = kb[D_DIM + tid];
    } else {
        const int j = tid - 128;
        vshf[j] = vb[j];
        if (S > 1) vshf[128 + j] = vb[D_DIM + j];
    }
    float pre = 0.0f;
    if (S > 2) pre = (tid < 128) ? kb[2 * (size_t)D_DIM + tid]
                                 : vb[2 * (size_t)D_DIM + (tid - 128)];
    __syncthreads();
    cluster_sync_all();   // peers' mbarriers + recv ready before DSMEM traffic

    // ---- pre-loop: ship zeros for token 0 (dots vs zero centroids) ----
    if (lane < 8) {
        const int r = lane;
        const int base_idx = rank * 66 + wid * 8;   // buf 0
        if (r == rank) {
            float* dst = recvf + base_idx;
            #pragma unroll
            for (int i = 0; i < 8; ++i) dst[i] = 0.0f;
            if (wid == 0) dst[64] = 0.0f;
        } else {
            const uint32_t ra = mapa_rank(sbase + OFF_RECV + (uint32_t)(base_idx * 4), (uint32_t)r);
            #pragma unroll
            for (int i = 0; i < 8; ++i) st_dsmem(ra + 4u * i, 0.0f);
            if (wid == 0) st_dsmem(ra + 4u * 64, 0.0f);
            mbar_arrive_remote(sbase + OFF_MBAR, (uint32_t)r);
        }
    }
    __syncthreads();

    // ---- warp0 carried decision state (identical on all CTAs) ----
    int   K_reg = 0, psl = -1, ppsl = -1, pcreate = 0;
    float pdenom = 1.0f, pkn2 = 0.0f, pdot = 0.0f;
    float kn2_t = 0.0f, kk_t = 0.0f, kn2_nx = 0.0f, kk_nx = 0.0f;
    if (wid == 0) { kn2_t = g_kn2[gbase]; kk_t = g_kk[gbase]; }

    for (int t = 0; t < S; ++t) {
        // ---- stage B: dots of k_{t+1} vs current centroids, ship one iter early ----
        if (t + 1 < S) {
            const float4 kq = ((const float4*)(kshf + ((t + 1) & 1) * 128))[lane];
            float p[8];
            #pragma unroll
            for (int i = 0; i < 8; ++i) {
                const float4 c4 = *((const float4*)(cent + (wid * 8 + i) * COLS) + lane);
                p[i] = kq.x * c4.x + kq.y * c4.y + kq.z * c4.z + kq.w * c4.w;
            }
            #pragma unroll
            for (int off = 16; off; off >>= 1) {
                #pragma unroll
                for (int i = 0; i < 8; ++i)
                    p[i] += __shfl_xor_sync(0xffffffffu, p[i], off);
            }
            if (lane < 8) {
                const int r = lane;
                float sqs = 0.0f;
                if (wid == 0) sqs = sq4[0] + sq4[1] + sq4[2] + sq4[3];
                const int buf = (t + 1) & 3;
                const int base_idx = buf * 528 + rank * 66 + wid * 8;
                if (r == rank) {
                    float* dst = recvf + base_idx;
                    #pragma unroll
                    for (int i = 0; i < 8; ++i) dst[i] = p[i];
                    if (wid == 0) dst[64] = sqs;
                } else {
                    const uint32_t ra = mapa_rank(sbase + OFF_RECV + (uint32_t)(base_idx * 4), (uint32_t)r);
                    #pragma unroll
                    for (int i = 0; i < 8; ++i) st_dsmem(ra + 4u * i, p[i]);
                    if (wid == 0) st_dsmem(ra + 4u * 64, sqs);
                    mbar_arrive_remote(sbase + OFF_MBAR + (uint32_t)(buf * 8), (uint32_t)r);
                }
            }
            if (wid == 0) {   // prefetch scalars for token t+1 (consumed next iter)
                kn2_nx = g_kn2[gbase + t + 1];
                kk_nx  = g_kk[gbase + t + 1];
            }
        }
        // prefetch token t+3
        float nxt = 0.0f;
        if (t + 3 < S)
            nxt = (tid < 128) ? kb[(size_t)(t + 3) * D_DIM + tid]
                              : vb[(size_t)(t + 3) * D_DIM + (tid - 128)];
        __syncthreads();   // local recv self-writes visible to warp0

        // ---- stage D: decide token t (dots were shipped one iteration ago) ----
        if (wid == 0) {
            mbar_wait_cluster(sbase + OFF_MBAR + (uint32_t)((t & 3) * 8),
                              (uint32_t)((t >> 2) & 1));
            const float* rcv = recvf + (t & 3) * 528;
            // exact cn2 overwrite for row updated two steps back
            if (ppsl >= 0) {
                float s = 0.0f;
                #pragma unroll
                for (int r = 0; r < 8; ++r) s += rcv[r * 66 + 64];
                if (lane == 0) cn2[ppsl] = s;
            }
            __syncwarp();
            // one-shot rank-1 correction for row updated last step
            if (psl >= 0) {
                float c;
                if (pcreate) c = pkn2;
                else {
                    const float inv = 1.0f / pdenom;
                    const float a = 1.0f - inv;
                    c = a * a * cn2[psl] + 2.0f * a * inv * pdot + pkn2 * inv * inv;
                }
                if (lane == 0) cn2[psl] = c;
            }
            __syncwarp();
            const int s1 = lane, s2 = lane + 32;
            float d1 = 0.0f, d2 = 0.0f;
            #pragma unroll
            for (int r = 0; r < 8; ++r) { d1 += rcv[r * 66 + s1]; d2 += rcv[r * 66 + s2]; }
            // rank-1 dot correction for row psl
            if (psl >= 0) {
                const float inv = 1.0f / pdenom;
                if (s1 == psl) d1 = pcreate ? kk_t : ((1.0f - inv) * d1 + kk_t * inv);
                if (s2 == psl) d2 = pcreate ? kk_t : ((1.0f - inv) * d2 + kk_t * inv);
            }
            const float rk = rsqrtf(kn2_t + EPS_F);
            const float v1 = (counts[s1] > 0.0f) ? d1 * rsqrtf(cn2[s1] + EPS_F) * rk : -3.0e38f;
            const float v2 = (counts[s2] > 0.0f) ? d2 * rsqrtf(cn2[s2] + EPS_F) * rk : -3.0e38f;
            float bv; int bi;
            if (v2 > v1) { bv = v2; bi = s2; } else { bv = v1; bi = s1; }
            #pragma unroll
            for (int off = 16; off; off >>= 1) {   // argmax, first-index tiebreak
                const float ov = __shfl_xor_sync(0xffffffffu, bv, off);
                const int   oi = __shfl_xor_sync(0xffffffffu, bi, off);
                if (ov > bv || (ov == bv && oi < bi)) { bv = ov; bi = oi; }
            }
            const int create = (K_reg == 0) || (bv < THRESH_F && K_reg < M_ST);
            const int slot = create ? K_reg : bi;
            const float n = counts[slot];
            const float denom = n + 1.0f;
            if (lane == 0) {
                counts[slot] = create ? 1.0f : denom;
                shi[0] = slot; shi[1] = create; *shden = denom;
            }
            // stash corrected dot at slot (unused when create)
            const float da = __shfl_sync(0xffffffffu, d1, slot & 31);
            const float db = __shfl_sync(0xffffffffu, d2, slot & 31);
            // shift carried state
            ppsl = psl; psl = slot; pcreate = create; pdenom = denom;
            pkn2 = kn2_t; pdot = (slot < 32) ? da : db;
            K_reg += create;
            kn2_t = kn2_nx; kk_t = kk_nx;
        }
        __syncthreads();

        // ---- stage E: update owned slices + publish token t+2 into freed buffers ----
        {
            const int slot = shi[0];
            const int create = shi[1];
            const float denom = *shden;
            const int bufp = (t & 1) * 128;
            if (tid < 128) {
                const float c = cent[slot * COLS + tid];
                const float k = kshf[bufp + tid];
                const float nc = create ? k : (c + (k - c) / denom);
                cent[slot * COLS + tid] = nc;
                float sq = nc * nc;
                #pragma unroll
                for (int off = 16; off; off >>= 1)
                    sq += __shfl_xor_sync(0xffffffffu, sq, off);
                if (lane == 0) sq4[wid] = sq;
                kshf[bufp + tid] = pre;          // token t+2
            } else {
                const int j = tid - 128;
                const float s = stat[slot * COLS + j];
                const float v = vshf[bufp + j];
                stat[slot * COLS + j] = create ? v : (s + (v - s) / denom);
                vshf[bufp + j] = pre;            // token t+2
            }
        }
        pre = nxt;
        __syncthreads();
    }

    // ---- flush states ----
    {
        const int half = tid >> 7;
        const int j = tid & 127;
        float* ob = out + (size_t)b * M_ST * D_DIM + c0;
        for (int s = half * 32; s < half * 32 + 32; ++s)
            ob[(size_t)s * D_DIM + j] = stat[s * COLS + j];
    }
    cluster_sync_all();   // keep SMEM alive until peers' remote ops settle
}

extern "C" void kernel_launch(void* const* d_in, const int* in_sizes, int n_in,
                              void* d_out, int out_size) {
    const float* keys   = (const float*)d_in[0];
    const float* values = (const float*)d_in[1];
    float* out = (float*)d_out;

    const int B = out_size / (M_ST * D_DIM);
    const int S = in_sizes[0] / (B * D_DIM);

    precompute_kernel<<<B * S, 256>>>(keys, S);

    cudaFuncSetAttribute(sparse_agg_kernel,
                         cudaFuncAttributeMaxDynamicSharedMemorySize, SMEM_BYTES);
    sparse_agg_kernel<<<B * RANKS, TPB, SMEM_BYTES>>>(keys, values, out, S);
}

// round 9
// speedup vs baseline: 1.0027x; 1.0027x over previous
#include <cuda_runtime.h>
#include <cstdint>

// SparseStateAggregator, pipelined: dots for token t+1 (vs C_{t-1}) are computed
// and all-gathered during iteration t; the decision for token t uses dots shipped
// one iteration earlier plus a rank-1 correction for the single row updated at t-1.
// kk[t]=dot(k_t,k_{t-1}) and kn2[t]=||k_t||^2 precomputed by a parallel kernel.

#define D_DIM   1024
#define M_ST    64
#define RANKS   8
#define COLS    128
#define TPB     256
#define THRESH_F 0.9f
#define EPS_F   1e-12f

// ---- shared memory layout (bytes) ----
#define OFF_MBAR   0       // 4 x u64 mbarriers (4-deep token ring)
#define OFF_INTS   32      // [0]=slot [1]=create
#define OFF_DENOM  48      // float
#define OFF_COUNTS 64      // 64 floats
#define OFF_CNORM2 320     // 64 floats
#define OFF_SQ4    576     // 4 floats (per-warp sq partials of updated cent row)
#define OFF_KSH    640     // 2 x 128 floats (ping-pong token keys)
#define OFF_VSH    1664    // 2 x 128 floats (ping-pong token values)
#define OFF_RECV   2688    // float recv[4][8][66]: 0..63 dot partials, 64 cn2 partial
#define OFF_CENT   11136   // 64*128 floats
#define OFF_STAT   43904   // 64*128 floats
#define SMEM_BYTES 76672

__device__ float g_kn2[65536];
__device__ float g_kk[65536];

static __device__ __forceinline__ uint32_t smem_u32(const void* p) {
    uint32_t a;
    asm("{ .reg .u64 t; cvta.to.shared.u64 t, %1; cvt.u32.u64 %0, t; }"
        : "=r"(a) : "l"(p));
    return a;
}
static __device__ __forceinline__ uint32_t mapa_rank(uint32_t addr, uint32_t rank) {
    uint32_t ra;
    asm("mapa.shared::cluster.u32 %0, %1, %2;" : "=r"(ra) : "r"(addr), "r"(rank));
    return ra;
}
static __device__ __forceinline__ void st_dsmem(uint32_t addr, float v) {
    asm volatile("st.shared::cluster.f32 [%0], %1;" :: "r"(addr), "f"(v) : "memory");
}
static __device__ __forceinline__ void mbar_init(uint32_t addr, uint32_t cnt) {
    asm volatile("mbarrier.init.shared.b64 [%0], %1;" :: "r"(addr), "r"(cnt) : "memory");
}
static __device__ __forceinline__ void mbar_arrive_remote(uint32_t local_mbar, uint32_t rank) {
    uint32_t ra = mapa_rank(local_mbar, rank);
    asm volatile("mbarrier.arrive.release.cluster.shared::cluster.b64 _, [%0];"
                 :: "r"(ra) : "memory");
}
static __device__ __forceinline__ void mbar_wait_cluster(uint32_t mbar, uint32_t parity) {
    asm volatile(
        "{\n\t"
        ".reg .pred P1;\n\t"
        "LAB_WAIT_%=:\n\t"
        "mbarrier.try_wait.parity.acquire.cluster.shared::cta.b64 P1, [%0], %1;\n\t"
        "@!P1 bra LAB_WAIT_%=;\n\t"
        "}\n"
        :: "r"(mbar), "r"(parity) : "memory");
}
static __device__ __forceinline__ void cluster_sync_all() {
    asm volatile("barrier.cluster.arrive.aligned;" ::: "memory");
    asm volatile("barrier.cluster.wait.aligned;" ::: "memory");
}

// ---- precompute: kn2[t]=||k_t||^2, kk[t]=dot(k_t,k_{t-1}) (kk[0]=0) ----
__global__ void __launch_bounds__(256) precompute_kernel(const float* __restrict__ keys, int S) {
    const int tok = blockIdx.x;
    const int t = tok - (tok / S) * S;
    const float4* kt = (const float4*)(keys + (size_t)tok * D_DIM);
    const float4 a = kt[threadIdx.x];
    float kn = a.x * a.x + a.y * a.y + a.z * a.z + a.w * a.w;
    float kk = 0.0f;
    if (t > 0) {
        const float4 p = ((const float4*)(keys + (size_t)(tok - 1) * D_DIM))[threadIdx.x];
        kk = a.x * p.x + a.y * p.y + a.z * p.z + a.w * p.w;
    }
    #pragma unroll
    for (int off = 16; off; off >>= 1) {
        kn += __shfl_xor_sync(0xffffffffu, kn, off);
        kk += __shfl_xor_sync(0xffffffffu, kk, off);
    }
    __shared__ float skn[8], skk[8];
    const int wid = threadIdx.x >> 5, lane = threadIdx.x & 31;
    if (lane == 0) { skn[wid] = kn; skk[wid] = kk; }
    __syncthreads();
    if (threadIdx.x == 0) {
        float a0 = 0.0f, b0 = 0.0f;
        #pragma unroll
        for (int i = 0; i < 8; ++i) { a0 += skn[i]; b0 += skk[i]; }
        g_kn2[tok] = a0; g_kk[tok] = b0;
    }
}

__global__ void __cluster_dims__(RANKS, 1, 1) __launch_bounds__(TPB, 1)
sparse_agg_kernel(const float* __restrict__ keys,
                  const float* __restrict__ values,
                  float* __restrict__ out, int S)
{
    extern __shared__ unsigned char sm[];
    const uint32_t sbase = smem_u32(sm);

    const int tid  = threadIdx.x;
    const int wid  = tid >> 5;
    const int lane = tid & 31;
    const int rank = blockIdx.x & (RANKS - 1);
    const int b    = blockIdx.x >> 3;
    const int c0   = rank * COLS;

    const float* kb = keys   + (size_t)b * S * D_DIM + c0;
    const float* vb = values + (size_t)b * S * D_DIM + c0;
    const size_t gbase = (size_t)b * S;

    float* cent   = (float*)(sm + OFF_CENT);
    float* stat   = (float*)(sm + OFF_STAT);
    float* counts = (float*)(sm + OFF_COUNTS);
    float* cn2    = (float*)(sm + OFF_CNORM2);
    float* sq4    = (float*)(sm + OFF_SQ4);
    float* kshf   = (float*)(sm + OFF_KSH);
    float* vshf   = (float*)(sm + OFF_VSH);
    float* recvf  = (float*)(sm + OFF_RECV);
    int*   shi    = (int*)  (sm + OFF_INTS);
    float* shden  = (float*)(sm + OFF_DENOM);

    // ---- init ----
    for (int i = tid; i < M_ST * COLS; i += TPB) { cent[i] = 0.0f; stat[i] = 0.0f; }
    for (int i = tid; i < M_ST; i += TPB) { counts[i] = 0.0f; cn2[i] = 0.0f; }
    for (int i = tid; i < 4 * 8 * 66; i += TPB) recvf[i] = 0.0f;
    if (tid < 4) sq4[tid] = 0.0f;
    if (tid == 0) {
        #pragma unroll
        for (int m = 0; m < 4; ++m)
            mbar_init(sbase + OFF_MBAR + 8u * m, 56);   // 7 peers * 8 warps
    }
    // preload tokens 0,1 into ping-pong buffers, token 2 into regs
    if (tid < 128) {
        kshf[tid] = kb[tid];
        if (S > 1) kshf[128 + tid] = kb[D_DIM + tid];
    } else {
        const int j = tid - 128;
        vshf[j] = vb[j];
        if (S > 1) vshf[128 + j] = vb[D_DIM + j];
    }
    float pre = 0.0f;
    if (S > 2) pre = (tid < 128) ? kb[2 * (size_t)D_DIM + tid]
                                 : vb[2 * (size_t)D_DIM + (tid - 128)];
    __syncthreads();
    cluster_sync_all();   // peers' mbarriers + recv ready before DSMEM traffic

    // ---- pre-loop: ship zeros for token 0 (dots vs zero centroids) ----
    if (lane < 8) {
        const int r = lane;
        const int base_idx = rank * 66 + wid * 8;   // buf 0
        if (r == rank) {
            float* dst = recvf + base_idx;
            #pragma unroll
            for (int i = 0; i < 8; ++i) dst[i] = 0.0f;
            if (wid == 0) dst[64] = 0.0f;
        } else {
            const uint32_t ra = mapa_rank(sbase + OFF_RECV + (uint32_t)(base_idx * 4), (uint32_t)r);
            #pragma unroll
            for (int i = 0; i < 8; ++i) st_dsmem(ra + 4u * i, 0.0f);
            if (wid == 0) st_dsmem(ra + 4u * 64, 0.0f);
            mbar_arrive_remote(sbase + OFF_MBAR, (uint32_t)r);
        }
    }
    __syncthreads();

    // ---- warp0 carried decision state (identical on all CTAs) ----
    int   K_reg = 0, psl = -1, ppsl = -1, pcreate = 0;
    float pdenom = 1.0f, pkn2 = 0.0f, pdot = 0.0f;
    float kn2_t = 0.0f, kk_t = 0.0f, kn2_nx = 0.0f, kk_nx = 0.0f;
    if (wid == 0) { kn2_t = g_kn2[gbase]; kk_t = g_kk[gbase]; }

    for (int t = 0; t < S; ++t) {
        // ---- stage B: dots of k_{t+1} vs current centroids, ship one iter early ----
        if (t + 1 < S) {
            const float4 kq = ((const float4*)(kshf + ((t + 1) & 1) * 128))[lane];
            float p[8];
            #pragma unroll
            for (int i = 0; i < 8; ++i) {
                const float4 c4 = *((const float4*)(cent + (wid * 8 + i) * COLS) + lane);
                p[i] = kq.x * c4.x + kq.y * c4.y + kq.z * c4.z + kq.w * c4.w;
            }
            #pragma unroll
            for (int off = 16; off; off >>= 1) {
                #pragma unroll
                for (int i = 0; i < 8; ++i)
                    p[i] += __shfl_xor_sync(0xffffffffu, p[i], off);
            }
            if (lane < 8) {
                const int r = lane;
                float sqs = 0.0f;
                if (wid == 0) sqs = sq4[0] + sq4[1] + sq4[2] + sq4[3];
                const int buf = (t + 1) & 3;
                const int base_idx = buf * 528 + rank * 66 + wid * 8;
                if (r == rank) {
                    float* dst = recvf + base_idx;
                    #pragma unroll
                    for (int i = 0; i < 8; ++i) dst[i] = p[i];
                    if (wid == 0) dst[64] = sqs;
                } else {
                    const uint32_t ra = mapa_rank(sbase + OFF_RECV + (uint32_t)(base_idx * 4), (uint32_t)r);
                    #pragma unroll
                    for (int i = 0; i < 8; ++i) st_dsmem(ra + 4u * i, p[i]);
                    if (wid == 0) st_dsmem(ra + 4u * 64, sqs);
                    mbar_arrive_remote(sbase + OFF_MBAR + (uint32_t)(buf * 8), (uint32_t)r);
                }
            }
            if (wid == 0) {   // prefetch scalars for token t+1 (consumed next iter)
                kn2_nx = g_kn2[gbase + t + 1];
                kk_nx  = g_kk[gbase + t + 1];
            }
        }
        // prefetch token t+3
        float nxt = 0.0f;
        if (t + 3 < S)
            nxt = (tid < 128) ? kb[(size_t)(t + 3) * D_DIM + tid]
                              : vb[(size_t)(t + 3) * D_DIM + (tid - 128)];
        __syncthreads();   // local recv self-writes visible to warp0

        // ---- stage D: decide token t (dots were shipped one iteration ago) ----
        if (wid == 0) {
            mbar_wait_cluster(sbase + OFF_MBAR + (uint32_t)((t & 3) * 8),
                              (uint32_t)((t >> 2) & 1));
            const float* rcv = recvf + (t & 3) * 528;
            // exact cn2 overwrite for row updated two steps back
            if (ppsl >= 0) {
                float s = 0.0f;
                #pragma unroll
                for (int r = 0; r < 8; ++r) s += rcv[r * 66 + 64];
                if (lane == 0) cn2[ppsl] = s;
            }
            __syncwarp();
            // one-shot rank-1 correction for row updated last step
            if (psl >= 0) {
                float c;
                if (pcreate) c = pkn2;
                else {
                    const float inv = 1.0f / pdenom;
                    const float a = 1.0f - inv;
                    c = a * a * cn2[psl] + 2.0f * a * inv * pdot + pkn2 * inv * inv;
                }
                if (lane == 0) cn2[psl] = c;
            }
            __syncwarp();
            const int s1 = lane, s2 = lane + 32;
            float d1 = 0.0f, d2 = 0.0f;
            #pragma unroll
            for (int r = 0; r < 8; ++r) { d1 += rcv[r * 66 + s1]; d2 += rcv[r * 66 + s2]; }
            // rank-1 dot correction for row psl
            if (psl >= 0) {
                const float inv = 1.0f / pdenom;
                if (s1 == psl) d1 = pcreate ? kk_t : ((1.0f - inv) * d1 + kk_t * inv);
                if (s2 == psl) d2 = pcreate ? kk_t : ((1.0f - inv) * d2 + kk_t * inv);
            }
            const float rk = rsqrtf(kn2_t + EPS_F);
            const float v1 = (counts[s1] > 0.0f) ? d1 * rsqrtf(cn2[s1] + EPS_F) * rk : -3.0e38f;
            const float v2 = (counts[s2] > 0.0f) ? d2 * rsqrtf(cn2[s2] + EPS_F) * rk : -3.0e38f;
            float bv; int bi;
            if (v2 > v1) { bv = v2; bi = s2; } else { bv = v1; bi = s1; }
            #pragma unroll
            for (int off = 16; off; off >>= 1) {   // argmax, first-index tiebreak
                const float ov = __shfl_xor_sync(0xffffffffu, bv, off);
                const int   oi = __shfl_xor_sync(0xffffffffu, bi, off);
                if (ov > bv || (ov == bv && oi < bi)) { bv = ov; bi = oi; }
            }
            const int create = (K_reg == 0) || (bv < THRESH_F && K_reg < M_ST);
            const int slot = create ? K_reg : bi;
            const float n = counts[slot];
            const float denom = n + 1.0f;
            if (lane == 0) {
                counts[slot] = create ? 1.0f : denom;
                shi[0] = slot; shi[1] = create; *shden = denom;
            }
            // stash corrected dot at slot (unused when create)
            const float da = __shfl_sync(0xffffffffu, d1, slot & 31);
            const float db = __shfl_sync(0xffffffffu, d2, slot & 31);
            // shift carried state
            ppsl = psl; psl = slot; pcreate = create; pdenom = denom;
            pkn2 = kn2_t; pdot = (slot < 32) ? da : db;
            K_reg += create;
            kn2_t = kn2_nx; kk_t = kk_nx;
        }
        __syncthreads();

        // ---- stage E: update owned slices + publish token t+2 into freed buffers ----
        {
            const int slot = shi[0];
            const int create = shi[1];
            const float denom = *shden;
            const int bufp = (t & 1) * 128;
            if (tid < 128) {
                const float c = cent[slot * COLS + tid];
                const float k = kshf[bufp + tid];
                const float nc = create ? k : (c + (k - c) / denom);
                cent[slot * COLS + tid] = nc;
                float sq = nc * nc;
                #pragma unroll
                for (int off = 16; off; off >>= 1)
                    sq += __shfl_xor_sync(0xffffffffu, sq, off);
                if (lane == 0) sq4[wid] = sq;
                kshf[bufp + tid] = pre;          // token t+2
            } else {
                const int j = tid - 128;
                const float s = stat[slot * COLS + j];
                const float v = vshf[bufp + j];
                stat[slot * COLS + j] = create ? v : (s + (v - s) / denom);
                vshf[bufp + j] = pre;            // token t+2
            }
        }
        pre = nxt;
        __syncthreads();
    }

    // ---- flush states ----
    {
        const int half = tid >> 7;
        const int j = tid & 127;
        float* ob = out + (size_t)b * M_ST * D_DIM + c0;
        for (int s = half * 32; s < half * 32 + 32; ++s)
            ob[(size_t)s * D_DIM + j] = stat[s * COLS + j];
    }
    cluster_sync_all();   // keep SMEM alive until peers' remote ops settle
}

extern "C" void kernel_launch(void* const* d_in, const int* in_sizes, int n_in,
                              void* d_out, int out_size) {
    const float* keys   = (const float*)d_in[0];
    const float* values = (const float*)d_in[1];
    float* out = (float*)d_out;

    const int B = out_size / (M_ST * D_DIM);
    const int S = in_sizes[0] / (B * D_DIM);

    precompute_kernel<<<B * S, 256>>>(keys, S);

    cudaFuncSetAttribute(sparse_agg_kernel,
                         cudaFuncAttributeMaxDynamicSharedMemorySize, SMEM_BYTES);
    sparse_agg_kernel<<<B * RANKS, TPB, SMEM_BYTES>>>(keys, values, out, S);
}

// round 10
// speedup vs baseline: 1.1649x; 1.1617x over previous
#include <cuda_runtime.h>
#include <cstdint>

// SparseStateAggregator: 8-CTA cluster per batch, 128 cols per CTA in SMEM.
// Per token: parallel partial dots -> DSMEM stores (disjoint addrs) ->
// ONE aggregated arrive per peer (7 total, distinct mbarriers) ->
// all 8 warps redundantly compute the identical decision from registers ->
// each warp updates its slice. 2 syncthreads/token, depth-2 buffers.

#define D_DIM   1024
#define M_ST    64
#define RANKS   8
#define COLS    128
#define TPB     256
#define THRESH_F 0.9f
#define EPS_F   1e-12f

// ---- shared memory layout (bytes) ----
#define OFF_MBAR   0       // 2 x u64 mbarriers (token-parity double buffer)
#define OFF_SQ4    16      // 4 floats: per-warp sq partials of updated cent row
#define OFF_KSH    32      // 2 x 128 floats (ping-pong token keys)
#define OFF_VSH    1056    // 2 x 128 floats (ping-pong token values)
#define OFF_RECV   2080    // float recv[2][8][68]: 0..63 dots, 64 |k|^2, 65 cn2 partial
#define OFF_CENT   6432    // 64*128 floats
#define OFF_STAT   39200   // 64*128 floats
#define SMEM_BYTES 71968

static __device__ __forceinline__ uint32_t smem_u32(const void* p) {
    uint32_t a;
    asm("{ .reg .u64 t; cvta.to.shared.u64 t, %1; cvt.u32.u64 %0, t; }"
        : "=r"(a) : "l"(p));
    return a;
}
static __device__ __forceinline__ uint32_t mapa_rank(uint32_t addr, uint32_t rank) {
    uint32_t ra;
    asm("mapa.shared::cluster.u32 %0, %1, %2;" : "=r"(ra) : "r"(addr), "r"(rank));
    return ra;
}
static __device__ __forceinline__ void st_dsmem(uint32_t addr, float v) {
    asm volatile("st.shared::cluster.f32 [%0], %1;" :: "r"(addr), "f"(v) : "memory");
}
static __device__ __forceinline__ void mbar_init(uint32_t addr, uint32_t cnt) {
    asm volatile("mbarrier.init.shared.b64 [%0], %1;" :: "r"(addr), "r"(cnt) : "memory");
}
static __device__ __forceinline__ void mbar_arrive_remote(uint32_t local_mbar, uint32_t rank) {
    uint32_t ra = mapa_rank(local_mbar, rank);
    asm volatile("mbarrier.arrive.release.cluster.shared::cluster.b64 _, [%0];"
                 :: "r"(ra) : "memory");
}
static __device__ __forceinline__ void mbar_wait_cluster(uint32_t mbar, uint32_t parity) {
    asm volatile(
        "{\n\t"
        ".reg .pred P1;\n\t"
        "LAB_WAIT_%=:\n\t"
        "mbarrier.try_wait.parity.acquire.cluster.shared::cta.b64 P1, [%0], %1;\n\t"
        "@!P1 bra LAB_WAIT_%=;\n\t"
        "}\n"
        :: "r"(mbar), "r"(parity) : "memory");
}
static __device__ __forceinline__ void cluster_sync_all() {
    asm volatile("barrier.cluster.arrive.aligned;" ::: "memory");
    asm volatile("barrier.cluster.wait.aligned;" ::: "memory");
}

__global__ void __cluster_dims__(RANKS, 1, 1) __launch_bounds__(TPB, 1)
sparse_agg_kernel(const float* __restrict__ keys,
                  const float* __restrict__ values,
                  float* __restrict__ out, int S)
{
    extern __shared__ unsigned char sm[];
    const uint32_t sbase = smem_u32(sm);

    const int tid  = threadIdx.x;
    const int wid  = tid >> 5;
    const int lane = tid & 31;
    const int rank = blockIdx.x & (RANKS - 1);
    const int b    = blockIdx.x >> 3;
    const int c0   = rank * COLS;

    const float* kb = keys   + (size_t)b * S * D_DIM + c0;
    const float* vb = values + (size_t)b * S * D_DIM + c0;

    float* sq4   = (float*)(sm + OFF_SQ4);
    float* kshf  = (float*)(sm + OFF_KSH);
    float* vshf  = (float*)(sm + OFF_VSH);
    float* recvf = (float*)(sm + OFF_RECV);
    float* cent  = (float*)(sm + OFF_CENT);
    float* stat  = (float*)(sm + OFF_STAT);

    // ---- init ----
    for (int i = tid; i < M_ST * COLS; i += TPB) { cent[i] = 0.0f; stat[i] = 0.0f; }
    for (int i = tid; i < 2 * 8 * 68; i += TPB) recvf[i] = 0.0f;
    if (tid < 4) sq4[tid] = 0.0f;
    if (tid == 0) {
        mbar_init(sbase + OFF_MBAR + 0, 7);   // one aggregated arrive per peer
        mbar_init(sbase + OFF_MBAR + 8, 7);
    }
    // load token 0 into buffer 0
    if (tid < 128) kshf[tid] = kb[tid];
    else           vshf[tid - 128] = vb[tid - 128];
    __syncthreads();
    cluster_sync_all();   // peers' mbarriers ready before any DSMEM traffic

    // ---- per-warp redundant decision state (identical across all warps/CTAs) ----
    int   K_reg = 0, psl = -1;
    float cnt0 = 0.0f, cnt1 = 0.0f;      // counts[lane], counts[lane+32]
    float cn2a = 0.0f, cn2b = 0.0f;      // cn2[lane],    cn2[lane+32]

    for (int t = 0; t < S; ++t) {
        const int buf = t & 1;

        // prefetch token t+1 from global (consumed in stage E)
        float pnx = 0.0f;
        if (t + 1 < S)
            pnx = (tid < 128) ? kb[(size_t)(t + 1) * D_DIM + tid]
                              : vb[(size_t)(t + 1) * D_DIM + (tid - 128)];

        // ---- stage B: partial dots over owned 128 cols + DSMEM all-gather ----
        {
            const float4 kq = ((const float4*)(kshf + buf * 128))[lane];
            float p[8];
            #pragma unroll
            for (int i = 0; i < 8; ++i) {
                const float4 c4 = *((const float4*)(cent + (wid * 8 + i) * COLS) + lane);
                p[i] = kq.x * c4.x + kq.y * c4.y + kq.z * c4.z + kq.w * c4.w;
            }
            #pragma unroll
            for (int off = 16; off; off >>= 1) {
                #pragma unroll
                for (int i = 0; i < 8; ++i)
                    p[i] += __shfl_xor_sync(0xffffffffu, p[i], off);
            }
            float p8 = 0.0f;
            if (wid == 0) {
                p8 = kq.x * kq.x + kq.y * kq.y + kq.z * kq.z + kq.w * kq.w;
                #pragma unroll
                for (int off = 16; off; off >>= 1)
                    p8 += __shfl_xor_sync(0xffffffffu, p8, off);
            }
            if (lane < 8) {          // lane r ships this warp's partials to CTA r
                const int r = lane;
                float sqs = 0.0f;
                if (wid == 0) sqs = sq4[0] + sq4[1] + sq4[2] + sq4[3];
                const int bidx = buf * 544 + rank * 68 + wid * 8;
                if (r == rank) {
                    float* dst = recvf + bidx;
                    #pragma unroll
                    for (int i = 0; i < 8; ++i) dst[i] = p[i];
                    if (wid == 0) { dst[64] = p8; dst[65] = sqs; }
                } else {
                    const uint32_t ra =
                        mapa_rank(sbase + OFF_RECV + (uint32_t)(bidx * 4), (uint32_t)r);
                    #pragma unroll
                    for (int i = 0; i < 8; ++i) st_dsmem(ra + 4u * i, p[i]);
                    if (wid == 0) { st_dsmem(ra + 256u, p8); st_dsmem(ra + 260u, sqs); }
                }
            }
        }
        __syncthreads();   // all local+remote stores issued; local recv visible

        // ---- aggregated arrival: ONE arrive per peer, 7 distinct mbarriers ----
        if (tid < 7) {
            asm volatile("fence.acq_rel.cluster;" ::: "memory");
            const int r = tid + (tid >= rank ? 1 : 0);
            mbar_arrive_remote(sbase + OFF_MBAR + (uint32_t)(buf * 8), (uint32_t)r);
        }
        mbar_wait_cluster(sbase + OFF_MBAR + (uint32_t)(buf * 8),
                          (uint32_t)((t >> 1) & 1));

        // ---- stage D: every warp computes the identical decision ----
        int slot, create;
        float denom;
        {
            const float* rcv = recvf + buf * 544;
            float s64 = 0.0f, s65 = 0.0f;
            #pragma unroll
            for (int r = 0; r < 8; ++r) {
                s64 += rcv[r * 68 + 64];
                s65 += rcv[r * 68 + 65];
            }
            // exact ||centroid||^2 refresh for the row updated last token
            if (psl >= 0) {
                if ((psl & 31) == lane) { if (psl < 32) cn2a = s65; else cn2b = s65; }
            }
            float d1 = 0.0f, d2 = 0.0f;
            #pragma unroll
            for (int r = 0; r < 8; ++r) {
                d1 += rcv[r * 68 + lane];
                d2 += rcv[r * 68 + 32 + lane];
            }
            const float rk = rsqrtf(s64 + EPS_F);
            const float v1 = (cnt0 > 0.0f) ? d1 * rsqrtf(cn2a + EPS_F) * rk : -3.0e38f;
            const float v2 = (cnt1 > 0.0f) ? d2 * rsqrtf(cn2b + EPS_F) * rk : -3.0e38f;
            float bv; int bi;
            if (v2 > v1) { bv = v2; bi = lane + 32; } else { bv = v1; bi = lane; }
            #pragma unroll
            for (int off = 16; off; off >>= 1) {   // argmax, first-index tiebreak
                const float ov = __shfl_xor_sync(0xffffffffu, bv, off);
                const int   oi = __shfl_xor_sync(0xffffffffu, bi, off);
                if (ov > bv || (ov == bv && oi < bi)) { bv = ov; bi = oi; }
            }
            create = (K_reg == 0) || (bv < THRESH_F && K_reg < M_ST);
            slot = create ? K_reg : bi;
            const float npre = (slot < 32)
                ? __shfl_sync(0xffffffffu, cnt0, slot)
                : __shfl_sync(0xffffffffu, cnt1, slot - 32);
            denom = npre + 1.0f;
            if (slot == lane)      cnt0 = create ? 1.0f : denom;
            if (slot == lane + 32) cnt1 = create ? 1.0f : denom;
            K_reg += create;
            psl = slot;
        }

        // ---- stage E: update owned slice + publish token t+1 ----
        if (tid < 128) {
            const float c = cent[slot * COLS + tid];
            const float k = kshf[buf * 128 + tid];
            const float nc = create ? k : (c + (k - c) / denom);
            cent[slot * COLS + tid] = nc;
            float sq = nc * nc;
            #pragma unroll
            for (int off = 16; off; off >>= 1)
                sq += __shfl_xor_sync(0xffffffffu, sq, off);
            if (lane == 0) sq4[wid] = sq;
            kshf[(buf ^ 1) * 128 + tid] = pnx;
        } else {
            const int j = tid - 128;
            const float s = stat[slot * COLS + j];
            const float v = vshf[buf * 128 + j];
            stat[slot * COLS + j] = create ? v : (s + (v - s) / denom);
            vshf[(buf ^ 1) * 128 + j] = pnx;
        }
        __syncthreads();   // E writes (cent/sq4/kshf/vshf) visible to next B
    }

    // ---- flush states ----
    {
        const int half = tid >> 7;
        const int j = tid & 127;
        float* ob = out + (size_t)b * M_ST * D_DIM + c0;
        for (int s = half * 32; s < half * 32 + 32; ++s)
            ob[(size_t)s * D_DIM + j] = stat[s * COLS + j];
    }
    cluster_sync_all();   // keep SMEM alive until peers' remote ops settle
}

extern "C" void kernel_launch(void* const* d_in, const int* in_sizes, int n_in,
                              void* d_out, int out_size) {
    const float* keys   = (const float*)d_in[0];
    const float* values = (const float*)d_in[1];
    float* out = (float*)d_out;

    const int B = out_size / (M_ST * D_DIM);
    const int S = in_sizes[0] / (B * D_DIM);

    cudaFuncSetAttribute(sparse_agg_kernel,
                         cudaFuncAttributeMaxDynamicSharedMemorySize, SMEM_BYTES);
    sparse_agg_kernel<<<B * RANKS, TPB, SMEM_BYTES>>>(keys, values, out, S);
}